// round 16
// baseline (speedup 1.0000x reference)
#include <cuda_runtime.h>
#include <cuda_fp16.h>
#include <cuda_bf16.h>

// Problem constants (match reference)
#define NN   100000      // nodes
#define FIN  128         // input features
#define HID  64          // hidden
#define NCLS 40          // classes
#define NE   1600000     // edges

#define CAP  64                           // per-node bucket capacity (P(overflow)~1e-14)
#define GEMM1_BLOCKS ((NN + 127) / 128)   // 782
#define BUK_BLOCKS 254                    // wave-1 residual next to gemm blocks

// Scratch (device globals — no allocation allowed)
__device__ int   g_is64;
__device__ int   g_pos [NN];          // statically zero; re-zeroed by dinv_scale
__device__ int   g_cnt [NN];          // node degree (from bucket pass)
__device__ int   g_esrc[NN * CAP];    // fixed-capacity adjacency: src lists per dst
__device__ float g_dinv[NN];
__device__ uint4 g_hs1h[NN * 8];      // x@W1 fp16 (scaled in place by dinv_scale)
__device__ uint4 g_acc1h[NN * 8];     // layer-1 aggregate, fp16
__device__ uint4 g_hs2h[NN * 5];      // (relu@W2)*dinv fp16: 40 halfs/row

// ---------------------------------------------------------------------------
// Packed f32x2 helpers (Blackwell FFMA2 — only reachable via PTX)
__device__ __forceinline__ unsigned long long pk2(float lo, float hi) {
    unsigned long long r;
    asm("mov.b64 %0, {%1, %2};" : "=l"(r) : "f"(lo), "f"(hi));
    return r;
}
__device__ __forceinline__ void fma2(unsigned long long& d,
                                     unsigned long long a, unsigned long long b) {
    asm("fma.rn.f32x2 %0, %1, %2, %0;" : "+l"(d) : "l"(a), "l"(b));
}
__device__ __forceinline__ void unpk2(unsigned long long v, float& x, float& y) {
    asm("mov.b64 {%0, %1}, %2;" : "=f"(x), "=f"(y) : "l"(v));
}

// fp16 uint4 -> 8 floats accumulate (scalar path)
__device__ __forceinline__ void acc8(float* a, uint4 v) {
    const __half2* hp = (const __half2*)&v;
#pragma unroll
    for (int q = 0; q < 4; q++) {
        float2 f = __half22float2(hp[q]);
        a[2 * q] += f.x; a[2 * q + 1] += f.y;
    }
}

// 4-row quad accumulate: fp16 pair-tree (HADD2) then fp32 accumulate.
__device__ __forceinline__ void acc8_quad(float* a, uint4 v0, uint4 v1,
                                          uint4 v2, uint4 v3) {
    const __half2* h0 = (const __half2*)&v0;
    const __half2* h1 = (const __half2*)&v1;
    const __half2* h2 = (const __half2*)&v2;
    const __half2* h3 = (const __half2*)&v3;
#pragma unroll
    for (int q = 0; q < 4; q++) {
        __half2 p01 = __hadd2(h0[q], h1[q]);
        __half2 p23 = __hadd2(h2[q], h3[q]);
        float2 f0 = __half22float2(p01);
        float2 f1 = __half22float2(p23);
        a[2 * q]     += f0.x + f1.x;
        a[2 * q + 1] += f0.y + f1.y;
    }
}

// ---------------------------------------------------------------------------
// Edge-index dtype detection (JAX silently downcasts int64 -> int32 by default)
__device__ __forceinline__ int edge_src(const void* __restrict__ ei, int e) {
    if (g_is64) return (int)((const long long*)ei)[e];
    return ((const int*)ei)[e];
}
__device__ __forceinline__ int edge_dst(const void* __restrict__ ei, int e) {
    if (g_is64) return (int)((const long long*)ei)[NE + e];
    return ((const int*)ei)[NE + e];
}

// Parallel dtype detect: 32 lanes x 8 words; any 8-byte word >= NN => int32.
__global__ void k_detect(const void* __restrict__ ei) {
    const unsigned long long* p = (const unsigned long long*)ei;
    int lane = threadIdx.x;
    bool bad = false;
#pragma unroll
    for (int i = 0; i < 8; i++)
        bad |= (p[lane * 8 + i] >= (unsigned long long)NN);
    unsigned m = __ballot_sync(0xFFFFFFFFu, bad);
    if (lane == 0) g_is64 = (m == 0) ? 1 : 0;
}

// ---------------------------------------------------------------------------
// FUSED: fixed-capacity bucket (blocks [0, BUK_BLOCKS)) + GEMM1 (rest).
__global__ void k_gemm1_bucket(const float* __restrict__ x,
                               const float* __restrict__ W1,
                               const void* __restrict__ ei) {
    __shared__ ulonglong2 Ws[FIN * HID / 4];  // 2048 entries = 32KB

    if (blockIdx.x < BUK_BLOCKS) {
        // --- bucket role: direct slotting, no offsets needed ---
        int t = blockIdx.x * blockDim.x + threadIdx.x;
        int stride = BUK_BLOCKS * blockDim.x;
        for (int e = t; e < NE; e += stride) {
            int s = edge_src(ei, e);
            int d = edge_dst(ei, e);
            int p = atomicAdd(&g_pos[d], 1);
            if (p < CAP) g_esrc[d * CAP + p] = s;
        }
        return;
    }

    // --- GEMM role (FMA-bound) ---
    for (int i = threadIdx.x; i < FIN * HID / 4; i += blockDim.x)
        Ws[i] = ((const ulonglong2*)W1)[i];
    __syncthreads();

    int row = (blockIdx.x - BUK_BLOCKS) * blockDim.x + threadIdx.x;
    if (row >= NN) return;

    unsigned long long acc[HID / 2];
#pragma unroll
    for (int c = 0; c < HID / 2; c++) acc[c] = 0ULL;

    const float4* xr = (const float4*)(x + (size_t)row * FIN);
#pragma unroll 2
    for (int k4 = 0; k4 < FIN / 4; k4++) {
        float4 xv = __ldg(xr + k4);
        float xk[4] = {xv.x, xv.y, xv.z, xv.w};
#pragma unroll
        for (int kk = 0; kk < 4; kk++) {
            unsigned long long xs2 = pk2(xk[kk], xk[kk]);
            const ulonglong2* wr = &Ws[(k4 * 4 + kk) * (HID / 4)];
#pragma unroll
            for (int c4 = 0; c4 < HID / 4; c4++) {
                ulonglong2 w = wr[c4];
                fma2(acc[c4 * 2 + 0], xs2, w.x);
                fma2(acc[c4 * 2 + 1], xs2, w.y);
            }
        }
    }

    uint4* h1 = &g_hs1h[row * 8];
#pragma unroll
    for (int j = 0; j < 8; j++) {
        uint4 v;
        unsigned int* vp = (unsigned int*)&v;
#pragma unroll
        for (int q = 0; q < 4; q++) {
            float lo, hi;
            unpk2(acc[4 * j + q], lo, hi);
            __half2 h = __floats2half2_rn(lo, hi);
            vp[q] = *(unsigned int*)&h;
        }
        h1[j] = v;
    }
}

// ---------------------------------------------------------------------------
// dinv + in-place scale: per (node, group) thread. cnt comes straight from
// the bucket counters. Also stores degree, resets g_pos for the next replay.
__global__ void k_dinv_scale() {
    int idx = blockIdx.x * blockDim.x + threadIdx.x;
    if (idx >= NN * 8) return;
    int d = idx >> 3, g = idx & 7;
    int cnt = g_pos[d];                       // broadcast load (8 lanes same addr)
    float di = rsqrtf((float)cnt + 1.0f);
    if (g == 0) {
        g_dinv[d] = di;
        g_cnt[d]  = cnt;
        g_pos[d]  = 0;
    }
    uint4 v = g_hs1h[idx];
    unsigned int* vp = (unsigned int*)&v;
#pragma unroll
    for (int q = 0; q < 4; q++) {
        __half2 h = *(__half2*)&vp[q];
        float2 f = __half22float2(h);
        h = __floats2half2_rn(f.x * di, f.y * di);
        vp[q] = *(unsigned int*)&h;
    }
    g_hs1h[idx] = v;
}

// ---------------------------------------------------------------------------
// Aggregation layer 1 — 256 threads = 32 nodes x 8 groups, smem-staged
// indices, and a one-deep software pipeline: quad j+1's gathers issue before
// quad j is accumulated, doubling in-flight LDGs per warp.
__global__ void __launch_bounds__(256) k_agg1() {
    __shared__ int sidx[32 * CAP];   // 8KB

    int base = blockIdx.x * 32;      // 3125 blocks * 32 nodes == NN exactly
    const int4* gl = (const int4*)&g_esrc[base * CAP];
    int4* sl = (int4*)sidx;
#pragma unroll
    for (int i = 0; i < 2; i++)
        sl[threadIdx.x + i * 256] = __ldg(&gl[threadIdx.x + i * 256]);
    __syncthreads();

    int d = base + (threadIdx.x >> 3), g = threadIdx.x & 7;
    int idx = d * 8 + g;
    int cnt = g_cnt[d];
    const int4* el4 = (const int4*)&sidx[(threadIdx.x >> 3) * CAP];

    float a[8];
#pragma unroll
    for (int q = 0; q < 8; q++) a[q] = 0.0f;
    acc8(a, g_hs1h[idx]);  // self term (pre-scaled by dinv[d])

    int nq = cnt >> 2;
    if (nq > 0) {
        int4 s4 = el4[0];
        uint4 v0 = __ldg(&g_hs1h[s4.x * 8 + g]);
        uint4 v1 = __ldg(&g_hs1h[s4.y * 8 + g]);
        uint4 v2 = __ldg(&g_hs1h[s4.z * 8 + g]);
        uint4 v3 = __ldg(&g_hs1h[s4.w * 8 + g]);
        for (int j4 = 1; j4 < nq; j4++) {
            int4 n4 = el4[j4];
            uint4 w0 = __ldg(&g_hs1h[n4.x * 8 + g]);
            uint4 w1 = __ldg(&g_hs1h[n4.y * 8 + g]);
            uint4 w2 = __ldg(&g_hs1h[n4.z * 8 + g]);
            uint4 w3 = __ldg(&g_hs1h[n4.w * 8 + g]);
            acc8_quad(a, v0, v1, v2, v3);
            v0 = w0; v1 = w1; v2 = w2; v3 = w3;
        }
        acc8_quad(a, v0, v1, v2, v3);
    }
    const int* el = (const int*)el4;
    for (int j = nq << 2; j < cnt; j++) {
        int s0 = el[j];
        acc8(a, __ldg(&g_hs1h[s0 * 8 + g]));
    }

    uint4 o;
    unsigned int* op = (unsigned int*)&o;
#pragma unroll
    for (int q = 0; q < 4; q++) {
        __half2 h = __floats2half2_rn(a[2 * q], a[2 * q + 1]);
        op[q] = *(unsigned int*)&h;
    }
    g_acc1h[idx] = o;
}

// ---------------------------------------------------------------------------
// GEMM2: in = relu(acc1[row]*dinv + b1); hs2 = (in @ W2) * dinv[row] as fp16.
__global__ void k_gemm2(const float* __restrict__ W2, const float* __restrict__ b1) {
    __shared__ ulonglong2 Ws[HID * NCLS / 4];  // 640 entries = 10KB
    __shared__ float b1s[HID];
    for (int i = threadIdx.x; i < HID * NCLS / 4; i += blockDim.x)
        Ws[i] = ((const ulonglong2*)W2)[i];
    for (int i = threadIdx.x; i < HID; i += blockDim.x) b1s[i] = b1[i];
    __syncthreads();

    int row = blockIdx.x * blockDim.x + threadIdx.x;
    if (row >= NN) return;

    float di = g_dinv[row];
    unsigned long long acc[NCLS / 2];
#pragma unroll
    for (int c = 0; c < NCLS / 2; c++) acc[c] = 0ULL;

    const uint4* ar = &g_acc1h[row * 8];
#pragma unroll
    for (int j = 0; j < 8; j++) {
        uint4 v = ar[j];
        const __half2* hp = (const __half2*)&v;
        float ak[8];
#pragma unroll
        for (int q = 0; q < 4; q++) {
            float2 f = __half22float2(hp[q]);
            ak[2 * q] = f.x; ak[2 * q + 1] = f.y;
        }
#pragma unroll
        for (int kk = 0; kk < 8; kk++) {
            int k = j * 8 + kk;
            float xv = fmaxf(ak[kk] * di + b1s[k], 0.0f);
            unsigned long long xs2 = pk2(xv, xv);
            const ulonglong2* wr = &Ws[k * (NCLS / 4)];
#pragma unroll
            for (int c4 = 0; c4 < NCLS / 4; c4++) {
                ulonglong2 w = wr[c4];
                fma2(acc[c4 * 2 + 0], xs2, w.x);
                fma2(acc[c4 * 2 + 1], xs2, w.y);
            }
        }
    }

    uint4* h2 = &g_hs2h[row * 5];
#pragma unroll
    for (int j = 0; j < 5; j++) {
        uint4 v;
        unsigned int* vp = (unsigned int*)&v;
#pragma unroll
        for (int q = 0; q < 4; q++) {
            float lo, hi;
            unpk2(acc[4 * j + q], lo, hi);
            __half2 h = __floats2half2_rn(lo * di, hi * di);
            vp[q] = *(unsigned int*)&h;
        }
        h2[j] = v;
    }
}

// ---------------------------------------------------------------------------
// Aggregation layer 2 + epilogue — thread per (node, 8-half group), direct
// int4 index loads (round-14 form: smem staging here was a measured loss),
// one-deep quad pipeline. out[d] = (hs2[d] + sum hs2[neigh])*dinv + b2.
__global__ void k_agg2(const float* __restrict__ b2, float* __restrict__ out) {
    int idx = blockIdx.x * blockDim.x + threadIdx.x;
    if (idx >= NN * 5) return;
    int d = idx / 5, g = idx - d * 5;
    int cnt = g_cnt[d];
    const int4* el4 = (const int4*)&g_esrc[d * CAP];

    float a[8];
#pragma unroll
    for (int q = 0; q < 8; q++) a[q] = 0.0f;
    acc8(a, g_hs2h[idx]);  // self term (idx == d*5+g)

    int nq = cnt >> 2;
    if (nq > 0) {
        int4 s4 = __ldg(&el4[0]);
        uint4 v0 = __ldg(&g_hs2h[s4.x * 5 + g]);
        uint4 v1 = __ldg(&g_hs2h[s4.y * 5 + g]);
        uint4 v2 = __ldg(&g_hs2h[s4.z * 5 + g]);
        uint4 v3 = __ldg(&g_hs2h[s4.w * 5 + g]);
        for (int j4 = 1; j4 < nq; j4++) {
            int4 n4 = __ldg(&el4[j4]);
            uint4 w0 = __ldg(&g_hs2h[n4.x * 5 + g]);
            uint4 w1 = __ldg(&g_hs2h[n4.y * 5 + g]);
            uint4 w2 = __ldg(&g_hs2h[n4.z * 5 + g]);
            uint4 w3 = __ldg(&g_hs2h[n4.w * 5 + g]);
            acc8_quad(a, v0, v1, v2, v3);
            v0 = w0; v1 = w1; v2 = w2; v3 = w3;
        }
        acc8_quad(a, v0, v1, v2, v3);
    }
    const int* el = (const int*)el4;
    for (int j = nq << 2; j < cnt; j++) {
        int s0 = __ldg(&el[j]);
        acc8(a, __ldg(&g_hs2h[s0 * 5 + g]));
    }

    float di = g_dinv[d];
    const float4* bp = (const float4*)(b2 + g * 8);
    float4 b0 = __ldg(bp), b1v = __ldg(bp + 1);
    float4* o = (float4*)(out + (size_t)d * NCLS + g * 8);
    o[0] = make_float4(a[0] * di + b0.x, a[1] * di + b0.y,
                       a[2] * di + b0.z, a[3] * di + b0.w);
    o[1] = make_float4(a[4] * di + b1v.x, a[5] * di + b1v.y,
                       a[6] * di + b1v.z, a[7] * di + b1v.w);
}

// ---------------------------------------------------------------------------
extern "C" void kernel_launch(void* const* d_in, const int* in_sizes, int n_in,
                              void* d_out, int out_size) {
    const float* x   = (const float*)d_in[0];
    const void*  ei  = d_in[1];                 // [2, NE], int32 OR int64
    const float* W1  = (const float*)d_in[2];
    const float* b1  = (const float*)d_in[3];
    const float* W2  = (const float*)d_in[4];
    const float* b2  = (const float*)d_in[5];
    float*       out = (float*)d_out;

    // dtype detect, then bucket (direct slotting) overlapped with GEMM1
    k_detect<<<1, 32>>>(ei);
    k_gemm1_bucket<<<BUK_BLOCKS + GEMM1_BLOCKS, 128>>>(x, W1, ei);

    // degree -> dinv, reset counters, scale hs1 in place
    k_dinv_scale<<<(NN * 8 + 255) / 256, 256>>>();

    // layer 1 aggregate: smem-staged indices, pipelined quad gather
    k_agg1<<<NN / 32, 256>>>();

    // layer 2 (relu fused into GEMM2 input; dinv+b2 fused into agg2)
    k_gemm2<<<(NN + 127) / 128, 128>>>(W2, b1);
    k_agg2<<<(NN * 5 + 319) / 320, 320>>>(b2, out);
}

// round 17
// speedup vs baseline: 1.5720x; 1.5720x over previous
#include <cuda_runtime.h>
#include <cuda_fp16.h>
#include <cuda_bf16.h>

// Problem constants (match reference)
#define NN   100000      // nodes
#define FIN  128         // input features
#define HID  64          // hidden
#define NCLS 40          // classes
#define NE   1600000     // edges

#define CAP  64                           // per-node bucket capacity (P(overflow)~1e-14)
#define GEMM1_BLOCKS ((NN + 127) / 128)   // 782
#define BUK_BLOCKS 254                    // wave-1 residual next to gemm blocks

// Scratch (device globals — no allocation allowed)
__device__ int   g_is64;
__device__ int   g_pos [NN];          // statically zero; re-zeroed by dinv_scale
__device__ int   g_cnt [NN];          // node degree (from bucket pass)
__device__ int   g_esrc[NN * CAP];    // fixed-capacity adjacency: src lists per dst
__device__ float g_dinv[NN];
__device__ uint4 g_hs1h[NN * 8];      // x@W1 fp16 (scaled in place by dinv_scale)
__device__ uint4 g_acc1h[NN * 8];     // layer-1 aggregate, fp16
__device__ uint4 g_hs2h[NN * 5];      // (relu@W2)*dinv fp16: 40 halfs/row

// ---------------------------------------------------------------------------
// Packed f32x2 helpers (Blackwell FFMA2 — only reachable via PTX)
__device__ __forceinline__ unsigned long long pk2(float lo, float hi) {
    unsigned long long r;
    asm("mov.b64 %0, {%1, %2};" : "=l"(r) : "f"(lo), "f"(hi));
    return r;
}
__device__ __forceinline__ void fma2(unsigned long long& d,
                                     unsigned long long a, unsigned long long b) {
    asm("fma.rn.f32x2 %0, %1, %2, %0;" : "+l"(d) : "l"(a), "l"(b));
}
__device__ __forceinline__ void unpk2(unsigned long long v, float& x, float& y) {
    asm("mov.b64 {%0, %1}, %2;" : "=f"(x), "=f"(y) : "l"(v));
}

// fp16 uint4 -> 8 floats accumulate (scalar path)
__device__ __forceinline__ void acc8(float* a, uint4 v) {
    const __half2* hp = (const __half2*)&v;
#pragma unroll
    for (int q = 0; q < 4; q++) {
        float2 f = __half22float2(hp[q]);
        a[2 * q] += f.x; a[2 * q + 1] += f.y;
    }
}

// 4-row quad accumulate: fp16 pair-tree (HADD2) then fp32 accumulate.
__device__ __forceinline__ void acc8_quad(float* a, uint4 v0, uint4 v1,
                                          uint4 v2, uint4 v3) {
    const __half2* h0 = (const __half2*)&v0;
    const __half2* h1 = (const __half2*)&v1;
    const __half2* h2 = (const __half2*)&v2;
    const __half2* h3 = (const __half2*)&v3;
#pragma unroll
    for (int q = 0; q < 4; q++) {
        __half2 p01 = __hadd2(h0[q], h1[q]);
        __half2 p23 = __hadd2(h2[q], h3[q]);
        float2 f0 = __half22float2(p01);
        float2 f1 = __half22float2(p23);
        a[2 * q]     += f0.x + f1.x;
        a[2 * q + 1] += f0.y + f1.y;
    }
}

// ---------------------------------------------------------------------------
// Edge-index dtype detection (JAX silently downcasts int64 -> int32 by default)
__device__ __forceinline__ int edge_src(const void* __restrict__ ei, int e) {
    if (g_is64) return (int)((const long long*)ei)[e];
    return ((const int*)ei)[e];
}
__device__ __forceinline__ int edge_dst(const void* __restrict__ ei, int e) {
    if (g_is64) return (int)((const long long*)ei)[NE + e];
    return ((const int*)ei)[NE + e];
}

// Parallel dtype detect: 32 lanes x 8 words; any 8-byte word >= NN => int32.
__global__ void k_detect(const void* __restrict__ ei) {
    const unsigned long long* p = (const unsigned long long*)ei;
    int lane = threadIdx.x;
    bool bad = false;
#pragma unroll
    for (int i = 0; i < 8; i++)
        bad |= (p[lane * 8 + i] >= (unsigned long long)NN);
    unsigned m = __ballot_sync(0xFFFFFFFFu, bad);
    if (lane == 0) g_is64 = (m == 0) ? 1 : 0;
}

// ---------------------------------------------------------------------------
// FUSED: fixed-capacity bucket (blocks [0, BUK_BLOCKS)) + GEMM1 (rest).
__global__ void k_gemm1_bucket(const float* __restrict__ x,
                               const float* __restrict__ W1,
                               const void* __restrict__ ei) {
    __shared__ ulonglong2 Ws[FIN * HID / 4];  // 2048 entries = 32KB

    if (blockIdx.x < BUK_BLOCKS) {
        // --- bucket role: direct slotting, no offsets needed ---
        int t = blockIdx.x * blockDim.x + threadIdx.x;
        int stride = BUK_BLOCKS * blockDim.x;
        for (int e = t; e < NE; e += stride) {
            int s = edge_src(ei, e);
            int d = edge_dst(ei, e);
            int p = atomicAdd(&g_pos[d], 1);
            if (p < CAP) g_esrc[d * CAP + p] = s;
        }
        return;
    }

    // --- GEMM role (FMA-bound) ---
    for (int i = threadIdx.x; i < FIN * HID / 4; i += blockDim.x)
        Ws[i] = ((const ulonglong2*)W1)[i];
    __syncthreads();

    int row = (blockIdx.x - BUK_BLOCKS) * blockDim.x + threadIdx.x;
    if (row >= NN) return;

    unsigned long long acc[HID / 2];
#pragma unroll
    for (int c = 0; c < HID / 2; c++) acc[c] = 0ULL;

    const float4* xr = (const float4*)(x + (size_t)row * FIN);
#pragma unroll 2
    for (int k4 = 0; k4 < FIN / 4; k4++) {
        float4 xv = __ldg(xr + k4);
        float xk[4] = {xv.x, xv.y, xv.z, xv.w};
#pragma unroll
        for (int kk = 0; kk < 4; kk++) {
            unsigned long long xs2 = pk2(xk[kk], xk[kk]);
            const ulonglong2* wr = &Ws[(k4 * 4 + kk) * (HID / 4)];
#pragma unroll
            for (int c4 = 0; c4 < HID / 4; c4++) {
                ulonglong2 w = wr[c4];
                fma2(acc[c4 * 2 + 0], xs2, w.x);
                fma2(acc[c4 * 2 + 1], xs2, w.y);
            }
        }
    }

    uint4* h1 = &g_hs1h[row * 8];
#pragma unroll
    for (int j = 0; j < 8; j++) {
        uint4 v;
        unsigned int* vp = (unsigned int*)&v;
#pragma unroll
        for (int q = 0; q < 4; q++) {
            float lo, hi;
            unpk2(acc[4 * j + q], lo, hi);
            __half2 h = __floats2half2_rn(lo, hi);
            vp[q] = *(unsigned int*)&h;
        }
        h1[j] = v;
    }
}

// ---------------------------------------------------------------------------
// dinv + in-place scale: per (node, group) thread. cnt comes straight from
// the bucket counters. Also stores degree, resets g_pos for the next replay.
__global__ void k_dinv_scale() {
    int idx = blockIdx.x * blockDim.x + threadIdx.x;
    if (idx >= NN * 8) return;
    int d = idx >> 3, g = idx & 7;
    int cnt = g_pos[d];                       // broadcast load (8 lanes same addr)
    float di = rsqrtf((float)cnt + 1.0f);
    if (g == 0) {
        g_dinv[d] = di;
        g_cnt[d]  = cnt;
        g_pos[d]  = 0;
    }
    uint4 v = g_hs1h[idx];
    unsigned int* vp = (unsigned int*)&v;
#pragma unroll
    for (int q = 0; q < 4; q++) {
        __half2 h = *(__half2*)&vp[q];
        float2 f = __half22float2(h);
        h = __floats2half2_rn(f.x * di, f.y * di);
        vp[q] = *(unsigned int*)&h;
    }
    g_hs1h[idx] = v;
}

// ---------------------------------------------------------------------------
// Aggregation layer 1 — 256 threads = 32 nodes x 8 groups, smem-staged
// indices (measured win: 29.9 -> 27.7us), plain non-pipelined quad loop
// (register-lean; pipelining was a measured loss).
__global__ void __launch_bounds__(256) k_agg1() {
    __shared__ int sidx[32 * CAP];   // 8KB

    int base = blockIdx.x * 32;      // 3125 blocks * 32 nodes == NN exactly
    const int4* gl = (const int4*)&g_esrc[base * CAP];
    int4* sl = (int4*)sidx;
#pragma unroll
    for (int i = 0; i < 2; i++)
        sl[threadIdx.x + i * 256] = __ldg(&gl[threadIdx.x + i * 256]);
    __syncthreads();

    int d = base + (threadIdx.x >> 3), g = threadIdx.x & 7;
    int idx = d * 8 + g;
    int cnt = g_cnt[d];
    const int4* el4 = (const int4*)&sidx[(threadIdx.x >> 3) * CAP];

    float a[8];
#pragma unroll
    for (int q = 0; q < 8; q++) a[q] = 0.0f;
    acc8(a, g_hs1h[idx]);  // self term (pre-scaled by dinv[d])

    int nq = cnt >> 2;
    for (int j4 = 0; j4 < nq; j4++) {
        int4 s4 = el4[j4];           // LDS broadcast within the node's 8 lanes
        uint4 v0 = __ldg(&g_hs1h[s4.x * 8 + g]);
        uint4 v1 = __ldg(&g_hs1h[s4.y * 8 + g]);
        uint4 v2 = __ldg(&g_hs1h[s4.z * 8 + g]);
        uint4 v3 = __ldg(&g_hs1h[s4.w * 8 + g]);
        acc8_quad(a, v0, v1, v2, v3);
    }
    const int* el = (const int*)el4;
    for (int j = nq << 2; j < cnt; j++) {
        int s0 = el[j];
        acc8(a, __ldg(&g_hs1h[s0 * 8 + g]));
    }

    uint4 o;
    unsigned int* op = (unsigned int*)&o;
#pragma unroll
    for (int q = 0; q < 4; q++) {
        __half2 h = __floats2half2_rn(a[2 * q], a[2 * q + 1]);
        op[q] = *(unsigned int*)&h;
    }
    g_acc1h[idx] = o;
}

// ---------------------------------------------------------------------------
// GEMM2: in = relu(acc1[row]*dinv + b1); hs2 = (in @ W2) * dinv[row] as fp16.
__global__ void k_gemm2(const float* __restrict__ W2, const float* __restrict__ b1) {
    __shared__ ulonglong2 Ws[HID * NCLS / 4];  // 640 entries = 10KB
    __shared__ float b1s[HID];
    for (int i = threadIdx.x; i < HID * NCLS / 4; i += blockDim.x)
        Ws[i] = ((const ulonglong2*)W2)[i];
    for (int i = threadIdx.x; i < HID; i += blockDim.x) b1s[i] = b1[i];
    __syncthreads();

    int row = blockIdx.x * blockDim.x + threadIdx.x;
    if (row >= NN) return;

    float di = g_dinv[row];
    unsigned long long acc[NCLS / 2];
#pragma unroll
    for (int c = 0; c < NCLS / 2; c++) acc[c] = 0ULL;

    const uint4* ar = &g_acc1h[row * 8];
#pragma unroll
    for (int j = 0; j < 8; j++) {
        uint4 v = ar[j];
        const __half2* hp = (const __half2*)&v;
        float ak[8];
#pragma unroll
        for (int q = 0; q < 4; q++) {
            float2 f = __half22float2(hp[q]);
            ak[2 * q] = f.x; ak[2 * q + 1] = f.y;
        }
#pragma unroll
        for (int kk = 0; kk < 8; kk++) {
            int k = j * 8 + kk;
            float xv = fmaxf(ak[kk] * di + b1s[k], 0.0f);
            unsigned long long xs2 = pk2(xv, xv);
            const ulonglong2* wr = &Ws[k * (NCLS / 4)];
#pragma unroll
            for (int c4 = 0; c4 < NCLS / 4; c4++) {
                ulonglong2 w = wr[c4];
                fma2(acc[c4 * 2 + 0], xs2, w.x);
                fma2(acc[c4 * 2 + 1], xs2, w.y);
            }
        }
    }

    uint4* h2 = &g_hs2h[row * 5];
#pragma unroll
    for (int j = 0; j < 5; j++) {
        uint4 v;
        unsigned int* vp = (unsigned int*)&v;
#pragma unroll
        for (int q = 0; q < 4; q++) {
            float lo, hi;
            unpk2(acc[4 * j + q], lo, hi);
            __half2 h = __floats2half2_rn(lo * di, hi * di);
            vp[q] = *(unsigned int*)&h;
        }
        h2[j] = v;
    }
}

// ---------------------------------------------------------------------------
// Aggregation layer 2 + epilogue — thread per (node, 8-half group), direct
// int4 index loads, non-pipelined quad (round-14 measured-best form).
// out[d] = (hs2[d] + sum hs2[neigh])*dinv + b2.
__global__ void k_agg2(const float* __restrict__ b2, float* __restrict__ out) {
    int idx = blockIdx.x * blockDim.x + threadIdx.x;
    if (idx >= NN * 5) return;
    int d = idx / 5, g = idx - d * 5;
    int cnt = g_cnt[d];
    const int4* el4 = (const int4*)&g_esrc[d * CAP];

    float a[8];
#pragma unroll
    for (int q = 0; q < 8; q++) a[q] = 0.0f;
    acc8(a, g_hs2h[idx]);  // self term (idx == d*5+g)

    int nq = cnt >> 2;
    for (int j4 = 0; j4 < nq; j4++) {
        int4 s4 = __ldg(&el4[j4]);
        uint4 v0 = __ldg(&g_hs2h[s4.x * 5 + g]);
        uint4 v1 = __ldg(&g_hs2h[s4.y * 5 + g]);
        uint4 v2 = __ldg(&g_hs2h[s4.z * 5 + g]);
        uint4 v3 = __ldg(&g_hs2h[s4.w * 5 + g]);
        acc8_quad(a, v0, v1, v2, v3);
    }
    const int* el = (const int*)el4;
    for (int j = nq << 2; j < cnt; j++) {
        int s0 = __ldg(&el[j]);
        acc8(a, __ldg(&g_hs2h[s0 * 5 + g]));
    }

    float di = g_dinv[d];
    const float4* bp = (const float4*)(b2 + g * 8);
    float4 b0 = __ldg(bp), b1v = __ldg(bp + 1);
    float4* o = (float4*)(out + (size_t)d * NCLS + g * 8);
    o[0] = make_float4(a[0] * di + b0.x, a[1] * di + b0.y,
                       a[2] * di + b0.z, a[3] * di + b0.w);
    o[1] = make_float4(a[4] * di + b1v.x, a[5] * di + b1v.y,
                       a[6] * di + b1v.z, a[7] * di + b1v.w);
}

// ---------------------------------------------------------------------------
extern "C" void kernel_launch(void* const* d_in, const int* in_sizes, int n_in,
                              void* d_out, int out_size) {
    const float* x   = (const float*)d_in[0];
    const void*  ei  = d_in[1];                 // [2, NE], int32 OR int64
    const float* W1  = (const float*)d_in[2];
    const float* b1  = (const float*)d_in[3];
    const float* W2  = (const float*)d_in[4];
    const float* b2  = (const float*)d_in[5];
    float*       out = (float*)d_out;

    // dtype detect, then bucket (direct slotting) overlapped with GEMM1
    k_detect<<<1, 32>>>(ei);
    k_gemm1_bucket<<<BUK_BLOCKS + GEMM1_BLOCKS, 128>>>(x, W1, ei);

    // degree -> dinv, reset counters, scale hs1 in place
    k_dinv_scale<<<(NN * 8 + 255) / 256, 256>>>();

    // layer 1 aggregate: smem-staged indices, plain quad HADD2 gather
    k_agg1<<<NN / 32, 256>>>();

    // layer 2 (relu fused into GEMM2 input; dinv+b2 fused into agg2)
    k_gemm2<<<(NN + 127) / 128, 128>>>(W2, b1);
    k_agg2<<<(NN * 5 + 319) / 320, 320>>>(b2, out);
}